// round 15
// baseline (speedup 1.0000x reference)
#include <cuda_runtime.h>
#include <cuda_bf16.h>
#include <cuda_fp16.h>
#include <cstdint>
#include <math.h>

// VectorQuantizer N=65536, D=64, K=512.
// R15: SINGLE kernel. R11's proven two-phase HMMA screen + exact rescore,
// with vq_prep folded into the B-fill (fp32 cb -> bf16 SW128 + f32 cnorm
// in-CTA) and vq_final folded via last-CTA reduction (threadfence+counter,
// self-resetting accumulators for graph replay).
// d_out: [0]=loss, [1..ND]=q_st, [1+ND]=ppl, [2+ND..)=idx.

#define D_DIM   64
#define K_CODES 512
#define M_TILE  128
#define TILES   512          // 65536 / 128
#define TPB     256
#define EPS     5e-3f        // >= 2x two-sided worst-case bf16 screen error
#define MAXC    24

typedef unsigned int u32;
typedef unsigned long long u64;

__device__ int    g_hist[K_CODES];   // reset by last CTA
__device__ double g_sse;             // reset by last CTA
__device__ u32    g_done;            // reset by last CTA

__device__ __forceinline__ u32 smem_u32(const void* p) {
    u32 a;
    asm("{ .reg .u64 t; cvta.to.shared.u64 t, %1; cvt.u32.u64 %0, t; }"
        : "=r"(a) : "l"(p));
    return a;
}
__device__ __forceinline__ u32 sw128(u32 b) { return b ^ ((b >> 3) & 0x70); }

__device__ __forceinline__ void ldsm_x4(u32& r0, u32& r1, u32& r2, u32& r3, u32 a) {
    asm volatile("ldmatrix.sync.aligned.m8n8.x4.shared.b16 {%0,%1,%2,%3}, [%4];"
                 : "=r"(r0), "=r"(r1), "=r"(r2), "=r"(r3) : "r"(a));
}
__device__ __forceinline__ void ldsm_x2(u32& r0, u32& r1, u32 a) {
    asm volatile("ldmatrix.sync.aligned.m8n8.x2.shared.b16 {%0,%1}, [%2];"
                 : "=r"(r0), "=r"(r1) : "r"(a));
}
__device__ __forceinline__ void mma16816(float& c0, float& c1, float& c2, float& c3,
                                         u32 a0, u32 a1, u32 a2, u32 a3,
                                         u32 b0, u32 b1) {
    asm volatile(
        "mma.sync.aligned.m16n8k16.row.col.f32.bf16.bf16.f32 "
        "{%0,%1,%2,%3}, {%4,%5,%6,%7}, {%8,%9}, {%0,%1,%2,%3};"
        : "+f"(c0), "+f"(c1), "+f"(c2), "+f"(c3)
        : "r"(a0), "r"(a1), "r"(a2), "r"(a3), "r"(b0), "r"(b1));
}

// ---- smem layout (bytes), ~100 KB -> 2 CTAs/SM ----
#define SM_A    0                        // 128 rows * 128B bf16 (SW128) = 16384
#define SM_B    16384                    // 512 rows * 128B bf16 (SW128) = 65536
#define SM_CN   81920                    // 512 f32 = 2048
#define SM_AN   83968                    // 128 f32 = 512
#define SM_AND  84480                    // 256 double (half norms) = 2048
#define SM_CNT  86528                    // 128 int = 512
#define SM_CAND 87040                    // 128*24 int = 12288
#define SM_KEY  99328                    // 128 u64 = 1024
#define SM_RED  100352                   // 8 double = 64
#define SM_LAST 100416                   // 1 u32 (+pad) = 64
#define SMEM_SZ 100480

// Exact fp32 score s = fl( fl(A - 2*dot) + C ), 4-chain fp32 dot.
__device__ __forceinline__ float exact_score(const float* __restrict__ cb,
                                             const float4* __restrict__ xr,
                                             float A, float C, int k) {
    const float4* cr = (const float4*)(cb + k * D_DIM);
    float a0 = 0.f, a1 = 0.f, a2 = 0.f, a3 = 0.f;
#pragma unroll
    for (int j = 0; j < D_DIM / 4; j++) {
        float4 cv = cr[j], xv = xr[j];
        a0 = __fmaf_rn(xv.x, cv.x, a0);
        a1 = __fmaf_rn(xv.y, cv.y, a1);
        a2 = __fmaf_rn(xv.z, cv.z, a2);
        a3 = __fmaf_rn(xv.w, cv.w, a3);
    }
    float dot = (a0 + a1) + (a2 + a3);
    return __fadd_rn(__fmaf_rn(-2.f, dot, A), C);
}

// ---------------------------------------------------------------------------
__global__ __launch_bounds__(TPB, 2)
void vq_main(const float* __restrict__ x, const float* __restrict__ cb,
             float* __restrict__ out, int nd) {
    extern __shared__ char smem[];
    const u32 sb  = smem_u32(smem);
    const int tid = threadIdx.x;
    const int lane = tid & 31;
    const int wrow = (tid >> 5) * 16;               // warp's first local row
    const int row  = tid & 127;                     // pair row
    const int half = tid >> 7;                      // 0: cols 0-31, 1: 32-63

    float* outq   = out + 1;
    float* outidx = out + 2 + nd;

    float*  scn  = (float*)(smem + SM_CN);
    float*  san  = (float*)(smem + SM_AN);
    double* sand = (double*)(smem + SM_AND);
    int*    scnt = (int*)(smem + SM_CNT);
    int*    scand= (int*)(smem + SM_CAND);
    u64*    skey = (u64*)(smem + SM_KEY);
    double* sred = (double*)(smem + SM_RED);
    u32*    slast= (u32*)(smem + SM_LAST);

    // B fill (prep folded): read fp32 cb, convert bf16 -> SW128 smem,
    // and compute f32 codebook norms (error ~1e-11 << 7.6e-6 tie grid).
#pragma unroll
    for (int rr = 0; rr < 2; rr++) {
        int r = tid * 2 + rr;
        const float4* src = (const float4*)(cb + r * D_DIM);
        float n0 = 0.f, n1 = 0.f, n2 = 0.f, n3 = 0.f;
#pragma unroll
        for (int j = 0; j < 8; j++) {
            float4 v = src[2 * j], w = src[2 * j + 1];
            n0 = __fmaf_rn(v.x, v.x, n0); n1 = __fmaf_rn(v.y, v.y, n1);
            n2 = __fmaf_rn(v.z, v.z, n2); n3 = __fmaf_rn(v.w, v.w, n3);
            n0 = __fmaf_rn(w.x, w.x, n0); n1 = __fmaf_rn(w.y, w.y, n1);
            n2 = __fmaf_rn(w.z, w.z, n2); n3 = __fmaf_rn(w.w, w.w, n3);
            __nv_bfloat162 b0 = __floats2bfloat162_rn(v.x, v.y);
            __nv_bfloat162 b1 = __floats2bfloat162_rn(v.z, v.w);
            __nv_bfloat162 b2 = __floats2bfloat162_rn(w.x, w.y);
            __nv_bfloat162 b3 = __floats2bfloat162_rn(w.z, w.w);
            uint4 pk = make_uint4(*(u32*)&b0, *(u32*)&b1, *(u32*)&b2, *(u32*)&b3);
            *(uint4*)(smem + SM_B + sw128((u32)r * 128 + j * 16)) = pk;
        }
        scn[r] = (n0 + n1) + (n2 + n3);
    }
    if (tid < M_TILE) { scnt[tid] = 0; skey[tid] = ~0ull; }

    // A: convert x half-rows to bf16 SW128 + half norms (all 256 threads)
    {
        const float4* gx = (const float4*)(x +
            ((size_t)blockIdx.x * M_TILE + row) * D_DIM + half * 32);
        double sa = 0.0;
#pragma unroll
        for (int j = 0; j < 8; j++) {
            float4 v = gx[j];
            sa += (double)__fmul_rn(v.x, v.x); sa += (double)__fmul_rn(v.y, v.y);
            sa += (double)__fmul_rn(v.z, v.z); sa += (double)__fmul_rn(v.w, v.w);
            __nv_bfloat162 p0 = __floats2bfloat162_rn(v.x, v.y);
            __nv_bfloat162 p1 = __floats2bfloat162_rn(v.z, v.w);
            u32 base = (u32)row * 128 + half * 64 + j * 8;
            *(u32*)(smem + SM_A + sw128(base))     = *(u32*)&p0;
            *(u32*)(smem + SM_A + sw128(base + 4)) = *(u32*)&p1;
        }
        sand[tid] = sa;
    }
    __syncthreads();
    if (tid < M_TILE) san[tid] = (float)(sand[tid] + sand[tid + 128]);
    __syncthreads();

    // ---- screening: each warp handles rows [wrow, wrow+16) x 512 codes ----
    {
        u32 af[4][4];
        {
            int r  = (lane & 7) + ((lane & 8) ? 8 : 0);
            int hh = (lane >> 4) & 1;
            u32 abase = (u32)(wrow + r) * 128 + hh * 16;
#pragma unroll
            for (int ks = 0; ks < 4; ks++)
                ldsm_x4(af[ks][0], af[ks][1], af[ks][2], af[ks][3],
                        sb + SM_A + sw128(abase + ks * 32));
        }
        const u32 bbase = (u32)(lane & 7) * 128 + ((lane >> 3) & 1) * 16;
        const int r0 = wrow + (lane >> 2);
        const int nlo = (lane & 3) * 2;

        // Phase 1: true row screen minima (branch-free)
        float tb0 = 3.4e38f, tb1 = 3.4e38f;
#pragma unroll 4
        for (int tile = 0; tile < 64; tile++) {
            float c0 = 0.f, c1 = 0.f, c2 = 0.f, c3 = 0.f;
            u32 tb_off = (u32)tile * 8 * 128;
#pragma unroll
            for (int ks = 0; ks < 4; ks++) {
                u32 b0, b1;
                ldsm_x2(b0, b1, sb + SM_B + sw128(tb_off + bbase + ks * 32));
                mma16816(c0, c1, c2, c3,
                         af[ks][0], af[ks][1], af[ks][2], af[ks][3], b0, b1);
            }
            int k0 = tile * 8 + nlo;
            float cn0 = scn[k0], cn1 = scn[k0 + 1];
            tb0 = fminf(tb0, fminf(__fmaf_rn(-2.f, c0, cn0),
                                   __fmaf_rn(-2.f, c1, cn1)));
            tb1 = fminf(tb1, fminf(__fmaf_rn(-2.f, c2, cn0),
                                   __fmaf_rn(-2.f, c3, cn1)));
        }
        tb0 = fminf(tb0, __shfl_xor_sync(0xFFFFFFFFu, tb0, 1));
        tb0 = fminf(tb0, __shfl_xor_sync(0xFFFFFFFFu, tb0, 2));
        tb1 = fminf(tb1, __shfl_xor_sync(0xFFFFFFFFu, tb1, 1));
        tb1 = fminf(tb1, __shfl_xor_sync(0xFFFFFFFFu, tb1, 2));
        const float thr0 = tb0 + EPS, thr1 = tb1 + EPS;

        // Phase 2: recompute, push candidates vs fixed thresholds
#pragma unroll 4
        for (int tile = 0; tile < 64; tile++) {
            float c0 = 0.f, c1 = 0.f, c2 = 0.f, c3 = 0.f;
            u32 tb_off = (u32)tile * 8 * 128;
#pragma unroll
            for (int ks = 0; ks < 4; ks++) {
                u32 b0, b1;
                ldsm_x2(b0, b1, sb + SM_B + sw128(tb_off + bbase + ks * 32));
                mma16816(c0, c1, c2, c3,
                         af[ks][0], af[ks][1], af[ks][2], af[ks][3], b0, b1);
            }
            int k0 = tile * 8 + nlo;
            float cn0 = scn[k0], cn1 = scn[k0 + 1];
            float t00 = __fmaf_rn(-2.f, c0, cn0);
            float t01 = __fmaf_rn(-2.f, c1, cn1);
            float t10 = __fmaf_rn(-2.f, c2, cn0);
            float t11 = __fmaf_rn(-2.f, c3, cn1);
            if (t00 < thr0) {
                int p = atomicAdd(&scnt[r0], 1);
                if (p < MAXC) scand[r0 * MAXC + p] = k0;
            }
            if (t01 < thr0) {
                int p = atomicAdd(&scnt[r0], 1);
                if (p < MAXC) scand[r0 * MAXC + p] = k0 + 1;
            }
            if (t10 < thr1) {
                int p = atomicAdd(&scnt[r0 + 8], 1);
                if (p < MAXC) scand[(r0 + 8) * MAXC + p] = k0;
            }
            if (t11 < thr1) {
                int p = atomicAdd(&scnt[r0 + 8], 1);
                if (p < MAXC) scand[(r0 + 8) * MAXC + p] = k0 + 1;
            }
        }
    }
    __syncthreads();

    // ---- exact rescore: pair-split candidates, u64-key argmin merge ----
    const int vid = blockIdx.x * M_TILE + row;
    const float4* xr = (const float4*)(x + (size_t)vid * D_DIM);
    {
        const float A = san[row];
        int nc = scnt[row];
        if (nc > MAXC) {                 // overflow: split full exact scan
            for (int k = half; k < K_CODES; k += 2) {
                float s = exact_score(cb, xr, A, scn[k], k);
                atomicMin(&skey[row], ((u64)__float_as_uint(s) << 32) | (u32)k);
            }
        } else {
            const int* cl = scand + row * MAXC;
            for (int i = half; i < nc; i += 2) {
                int k = cl[i];
                float s = exact_score(cb, xr, A, scn[k], k);
                // s > 0 (dist^2 ~ 64): float-bits order == value order.
                atomicMin(&skey[row], ((u64)__float_as_uint(s) << 32) | (u32)k);
            }
        }
    }
    __syncthreads();

    const int bi = (int)(u32)skey[row];
    if (half == 0) {
        outidx[vid] = (float)bi;
        atomicAdd(&g_hist[bi], 1);
    }

    // ---- epilogue: 2 threads/row, 32 floats each ----
    // quantized_st = x + (q - x); SSE of (q - x)^2.
    // outq is d_out+1 (odd float offset): scalar 32-bit stores only.
    float sse = 0.f;
    {
        const float4* qr = (const float4*)(cb + bi * D_DIM) + half * 8;
        const float4* xh = xr + half * 8;
        float* o = outq + (size_t)vid * D_DIM + half * 32;
#pragma unroll
        for (int j = 0; j < 8; j++) {
            float4 qv = qr[j], xv = xh[j];
            float d0 = __fadd_rn(qv.x, -xv.x), d1 = __fadd_rn(qv.y, -xv.y);
            float d2 = __fadd_rn(qv.z, -xv.z), d3 = __fadd_rn(qv.w, -xv.w);
            sse += d0 * d0 + d1 * d1 + d2 * d2 + d3 * d3;
            o[4 * j]     = __fadd_rn(xv.x, d0);
            o[4 * j + 1] = __fadd_rn(xv.y, d1);
            o[4 * j + 2] = __fadd_rn(xv.z, d2);
            o[4 * j + 3] = __fadd_rn(xv.w, d3);
        }
    }

    // Block-reduce SSE -> one double atomic per CTA
#pragma unroll
    for (int o = 16; o > 0; o >>= 1)
        sse += __shfl_xor_sync(0xFFFFFFFFu, sse, o);
    if ((tid & 31) == 0) sred[tid >> 5] = (double)sse;
    __syncthreads();
    if (tid == 0) {
        double s = 0.0;
#pragma unroll
        for (int w = 0; w < 8; w++) s += sred[w];
        atomicAdd(&g_sse, s);
        __threadfence();
        slast[0] = (atomicAdd(&g_done, 1u) == (u32)(TILES - 1));
    }
    __syncthreads();

    // ---- last CTA: finalize loss + perplexity, reset accumulators ----
    if (slast[0]) {
        __threadfence();
        // code t*? : each thread handles codes tid and tid+256.
        // atomicAdd(,0) read bypasses any stale L1 line.
        int h0 = atomicAdd(&g_hist[tid], 0);
        int h1 = atomicAdd(&g_hist[tid + 256], 0);
        const float n = (float)(nd / D_DIM);
        float p0 = (float)h0 / n, p1 = (float)h1 / n;
        float e = p0 * logf(p0 + 1e-10f) + p1 * logf(p1 + 1e-10f);
#pragma unroll
        for (int o = 16; o > 0; o >>= 1)
            e += __shfl_xor_sync(0xFFFFFFFFu, e, o);
        float* red = (float*)sred;   // reuse (sse phase done)
        __syncthreads();
        if ((tid & 31) == 0) red[tid >> 5] = e;
        __syncthreads();
        if (tid == 0) {
            float v = red[0] + red[1] + red[2] + red[3] +
                      red[4] + red[5] + red[6] + red[7];
            double ssum = atomicAdd(&g_sse, 0.0);
            out[1 + nd] = expf(-v);                // perplexity
            float m = (float)(ssum / (double)nd);  // mean squared error
            out[0] = m + 0.25f * m;                // q_loss + 0.25*e_loss
            g_sse = 0.0;                           // reset for next replay
            g_done = 0;
        }
        g_hist[tid] = 0;
        g_hist[tid + 256] = 0;
    }
}

// ---------------------------------------------------------------------------
extern "C" void kernel_launch(void* const* d_in, const int* in_sizes, int n_in,
                              void* d_out, int out_size) {
    const float* x  = (const float*)d_in[0];
    const float* cb = (const float*)d_in[1];
    float* out = (float*)d_out;

    int nd = in_sizes[0];   // 4194304

    cudaFuncSetAttribute(vq_main, cudaFuncAttributeMaxDynamicSharedMemorySize,
                         SMEM_SZ);

    vq_main<<<TILES, TPB, SMEM_SZ>>>(x, cb, out, nd);
}

// round 16
// speedup vs baseline: 1.0302x; 1.0302x over previous
#include <cuda_runtime.h>
#include <cuda_bf16.h>
#include <cuda_fp16.h>
#include <cstdint>
#include <math.h>

// VectorQuantizer N=65536, D=64, K=512.
// R16: R15 single kernel, screen restructured to ldmatrix.x4 B-pairing:
// each iteration loads B frags for TWO n8 tiles in one LDSM (halves LDSM
// issue) and runs two independent accumulator quads (doubles MMA ILP).
// d_out: [0]=loss, [1..ND]=q_st, [1+ND]=ppl, [2+ND..)=idx.

#define D_DIM   64
#define K_CODES 512
#define M_TILE  128
#define TILES   512          // 65536 / 128
#define TPB     256
#define EPS     5e-3f        // >= 2x two-sided worst-case bf16 screen error
#define MAXC    24

typedef unsigned int u32;
typedef unsigned long long u64;

__device__ int    g_hist[K_CODES];   // reset by last CTA
__device__ double g_sse;             // reset by last CTA
__device__ u32    g_done;            // reset by last CTA

__device__ __forceinline__ u32 smem_u32(const void* p) {
    u32 a;
    asm("{ .reg .u64 t; cvta.to.shared.u64 t, %1; cvt.u32.u64 %0, t; }"
        : "=r"(a) : "l"(p));
    return a;
}
__device__ __forceinline__ u32 sw128(u32 b) { return b ^ ((b >> 3) & 0x70); }

__device__ __forceinline__ void ldsm_x4(u32& r0, u32& r1, u32& r2, u32& r3, u32 a) {
    asm volatile("ldmatrix.sync.aligned.m8n8.x4.shared.b16 {%0,%1,%2,%3}, [%4];"
                 : "=r"(r0), "=r"(r1), "=r"(r2), "=r"(r3) : "r"(a));
}
__device__ __forceinline__ void mma16816(float& c0, float& c1, float& c2, float& c3,
                                         u32 a0, u32 a1, u32 a2, u32 a3,
                                         u32 b0, u32 b1) {
    asm volatile(
        "mma.sync.aligned.m16n8k16.row.col.f32.bf16.bf16.f32 "
        "{%0,%1,%2,%3}, {%4,%5,%6,%7}, {%8,%9}, {%0,%1,%2,%3};"
        : "+f"(c0), "+f"(c1), "+f"(c2), "+f"(c3)
        : "r"(a0), "r"(a1), "r"(a2), "r"(a3), "r"(b0), "r"(b1));
}

// ---- smem layout (bytes), ~100 KB -> 2 CTAs/SM ----
#define SM_A    0                        // 128 rows * 128B bf16 (SW128) = 16384
#define SM_B    16384                    // 512 rows * 128B bf16 (SW128) = 65536
#define SM_CN   81920                    // 512 f32 = 2048
#define SM_AN   83968                    // 128 f32 = 512
#define SM_AND  84480                    // 256 double (half norms) = 2048
#define SM_CNT  86528                    // 128 int = 512
#define SM_CAND 87040                    // 128*24 int = 12288
#define SM_KEY  99328                    // 128 u64 = 1024
#define SM_RED  100352                   // 8 double = 64
#define SM_LAST 100416                   // 1 u32 (+pad) = 64
#define SMEM_SZ 100480

// Exact fp32 score s = fl( fl(A - 2*dot) + C ), 4-chain fp32 dot.
__device__ __forceinline__ float exact_score(const float* __restrict__ cb,
                                             const float4* __restrict__ xr,
                                             float A, float C, int k) {
    const float4* cr = (const float4*)(cb + k * D_DIM);
    float a0 = 0.f, a1 = 0.f, a2 = 0.f, a3 = 0.f;
#pragma unroll
    for (int j = 0; j < D_DIM / 4; j++) {
        float4 cv = cr[j], xv = xr[j];
        a0 = __fmaf_rn(xv.x, cv.x, a0);
        a1 = __fmaf_rn(xv.y, cv.y, a1);
        a2 = __fmaf_rn(xv.z, cv.z, a2);
        a3 = __fmaf_rn(xv.w, cv.w, a3);
    }
    float dot = (a0 + a1) + (a2 + a3);
    return __fadd_rn(__fmaf_rn(-2.f, dot, A), C);
}

// ---------------------------------------------------------------------------
__global__ __launch_bounds__(TPB, 2)
void vq_main(const float* __restrict__ x, const float* __restrict__ cb,
             float* __restrict__ out, int nd) {
    extern __shared__ char smem[];
    const u32 sb  = smem_u32(smem);
    const int tid = threadIdx.x;
    const int lane = tid & 31;
    const int wrow = (tid >> 5) * 16;               // warp's first local row
    const int row  = tid & 127;                     // pair row
    const int half = tid >> 7;                      // 0: cols 0-31, 1: 32-63

    float* outq   = out + 1;
    float* outidx = out + 2 + nd;

    float*  scn  = (float*)(smem + SM_CN);
    float*  san  = (float*)(smem + SM_AN);
    double* sand = (double*)(smem + SM_AND);
    int*    scnt = (int*)(smem + SM_CNT);
    int*    scand= (int*)(smem + SM_CAND);
    u64*    skey = (u64*)(smem + SM_KEY);
    double* sred = (double*)(smem + SM_RED);
    u32*    slast= (u32*)(smem + SM_LAST);

    // B fill (prep folded): fp32 cb -> bf16 SW128 smem + f32 cnorm.
#pragma unroll
    for (int rr = 0; rr < 2; rr++) {
        int r = tid * 2 + rr;
        const float4* src = (const float4*)(cb + r * D_DIM);
        float n0 = 0.f, n1 = 0.f, n2 = 0.f, n3 = 0.f;
#pragma unroll
        for (int j = 0; j < 8; j++) {
            float4 v = src[2 * j], w = src[2 * j + 1];
            n0 = __fmaf_rn(v.x, v.x, n0); n1 = __fmaf_rn(v.y, v.y, n1);
            n2 = __fmaf_rn(v.z, v.z, n2); n3 = __fmaf_rn(v.w, v.w, n3);
            n0 = __fmaf_rn(w.x, w.x, n0); n1 = __fmaf_rn(w.y, w.y, n1);
            n2 = __fmaf_rn(w.z, w.z, n2); n3 = __fmaf_rn(w.w, w.w, n3);
            __nv_bfloat162 b0 = __floats2bfloat162_rn(v.x, v.y);
            __nv_bfloat162 b1 = __floats2bfloat162_rn(v.z, v.w);
            __nv_bfloat162 b2 = __floats2bfloat162_rn(w.x, w.y);
            __nv_bfloat162 b3 = __floats2bfloat162_rn(w.z, w.w);
            uint4 pk = make_uint4(*(u32*)&b0, *(u32*)&b1, *(u32*)&b2, *(u32*)&b3);
            *(uint4*)(smem + SM_B + sw128((u32)r * 128 + j * 16)) = pk;
        }
        scn[r] = (n0 + n1) + (n2 + n3);
    }
    if (tid < M_TILE) { scnt[tid] = 0; skey[tid] = ~0ull; }

    // A: convert x half-rows to bf16 SW128 + half norms (all 256 threads)
    {
        const float4* gx = (const float4*)(x +
            ((size_t)blockIdx.x * M_TILE + row) * D_DIM + half * 32);
        double sa = 0.0;
#pragma unroll
        for (int j = 0; j < 8; j++) {
            float4 v = gx[j];
            sa += (double)__fmul_rn(v.x, v.x); sa += (double)__fmul_rn(v.y, v.y);
            sa += (double)__fmul_rn(v.z, v.z); sa += (double)__fmul_rn(v.w, v.w);
            __nv_bfloat162 p0 = __floats2bfloat162_rn(v.x, v.y);
            __nv_bfloat162 p1 = __floats2bfloat162_rn(v.z, v.w);
            u32 base = (u32)row * 128 + half * 64 + j * 8;
            *(u32*)(smem + SM_A + sw128(base))     = *(u32*)&p0;
            *(u32*)(smem + SM_A + sw128(base + 4)) = *(u32*)&p1;
        }
        sand[tid] = sa;
    }
    __syncthreads();
    if (tid < M_TILE) san[tid] = (float)(sand[tid] + sand[tid + 128]);
    __syncthreads();

    // ---- screening: each warp handles rows [wrow, wrow+16) x 512 codes ----
    {
        u32 af[4][4];
        {
            int r  = (lane & 7) + ((lane & 8) ? 8 : 0);
            int hh = (lane >> 4) & 1;
            u32 abase = (u32)(wrow + r) * 128 + hh * 16;
#pragma unroll
            for (int ks = 0; ks < 4; ks++)
                ldsm_x4(af[ks][0], af[ks][1], af[ks][2], af[ks][3],
                        sb + SM_A + sw128(abase + ks * 32));
        }
        // x4 B addressing: groups 0/1 -> even tile (b0/b1), 2/3 -> odd tile
        const u32 bbase4 = (u32)(lane & 7) * 128 + ((lane >> 3) & 1) * 16
                         + (u32)(lane >> 4) * 1024;
        const int r0 = wrow + (lane >> 2);
        const int nlo = (lane & 3) * 2;

        // Phase 1: true row screen minima, tile-pair loop (branch-free)
        float tb0 = 3.4e38f, tb1 = 3.4e38f;
#pragma unroll 2
        for (int pr = 0; pr < 32; pr++) {
            float e0 = 0.f, e1 = 0.f, e2 = 0.f, e3 = 0.f;
            float o0 = 0.f, o1 = 0.f, o2 = 0.f, o3 = 0.f;
            u32 pb = (u32)pr * 2048;
#pragma unroll
            for (int ks = 0; ks < 4; ks++) {
                u32 b0, b1, b2, b3;
                ldsm_x4(b0, b1, b2, b3, sb + SM_B + sw128(pb + bbase4 + ks * 32));
                mma16816(e0, e1, e2, e3,
                         af[ks][0], af[ks][1], af[ks][2], af[ks][3], b0, b1);
                mma16816(o0, o1, o2, o3,
                         af[ks][0], af[ks][1], af[ks][2], af[ks][3], b2, b3);
            }
            int k0 = pr * 16 + nlo;                 // even tile
            int k1 = k0 + 8;                        // odd tile
            float cnE0 = scn[k0], cnE1 = scn[k0 + 1];
            float cnO0 = scn[k1], cnO1 = scn[k1 + 1];
            tb0 = fminf(tb0, fminf(fminf(__fmaf_rn(-2.f, e0, cnE0),
                                         __fmaf_rn(-2.f, e1, cnE1)),
                                   fminf(__fmaf_rn(-2.f, o0, cnO0),
                                         __fmaf_rn(-2.f, o1, cnO1))));
            tb1 = fminf(tb1, fminf(fminf(__fmaf_rn(-2.f, e2, cnE0),
                                         __fmaf_rn(-2.f, e3, cnE1)),
                                   fminf(__fmaf_rn(-2.f, o2, cnO0),
                                         __fmaf_rn(-2.f, o3, cnO1))));
        }
        tb0 = fminf(tb0, __shfl_xor_sync(0xFFFFFFFFu, tb0, 1));
        tb0 = fminf(tb0, __shfl_xor_sync(0xFFFFFFFFu, tb0, 2));
        tb1 = fminf(tb1, __shfl_xor_sync(0xFFFFFFFFu, tb1, 1));
        tb1 = fminf(tb1, __shfl_xor_sync(0xFFFFFFFFu, tb1, 2));
        const float thr0 = tb0 + EPS, thr1 = tb1 + EPS;

        // Phase 2: recompute (paired), push candidates vs fixed thresholds
#pragma unroll 2
        for (int pr = 0; pr < 32; pr++) {
            float e0 = 0.f, e1 = 0.f, e2 = 0.f, e3 = 0.f;
            float o0 = 0.f, o1 = 0.f, o2 = 0.f, o3 = 0.f;
            u32 pb = (u32)pr * 2048;
#pragma unroll
            for (int ks = 0; ks < 4; ks++) {
                u32 b0, b1, b2, b3;
                ldsm_x4(b0, b1, b2, b3, sb + SM_B + sw128(pb + bbase4 + ks * 32));
                mma16816(e0, e1, e2, e3,
                         af[ks][0], af[ks][1], af[ks][2], af[ks][3], b0, b1);
                mma16816(o0, o1, o2, o3,
                         af[ks][0], af[ks][1], af[ks][2], af[ks][3], b2, b3);
            }
            int k0 = pr * 16 + nlo;
            int k1 = k0 + 8;
            float cnE0 = scn[k0], cnE1 = scn[k0 + 1];
            float cnO0 = scn[k1], cnO1 = scn[k1 + 1];
            float tE0 = __fmaf_rn(-2.f, e0, cnE0);
            float tE1 = __fmaf_rn(-2.f, e1, cnE1);
            float tE2 = __fmaf_rn(-2.f, e2, cnE0);
            float tE3 = __fmaf_rn(-2.f, e3, cnE1);
            float tO0 = __fmaf_rn(-2.f, o0, cnO0);
            float tO1 = __fmaf_rn(-2.f, o1, cnO1);
            float tO2 = __fmaf_rn(-2.f, o2, cnO0);
            float tO3 = __fmaf_rn(-2.f, o3, cnO1);
            if (tE0 < thr0) {
                int p = atomicAdd(&scnt[r0], 1);
                if (p < MAXC) scand[r0 * MAXC + p] = k0;
            }
            if (tE1 < thr0) {
                int p = atomicAdd(&scnt[r0], 1);
                if (p < MAXC) scand[r0 * MAXC + p] = k0 + 1;
            }
            if (tO0 < thr0) {
                int p = atomicAdd(&scnt[r0], 1);
                if (p < MAXC) scand[r0 * MAXC + p] = k1;
            }
            if (tO1 < thr0) {
                int p = atomicAdd(&scnt[r0], 1);
                if (p < MAXC) scand[r0 * MAXC + p] = k1 + 1;
            }
            if (tE2 < thr1) {
                int p = atomicAdd(&scnt[r0 + 8], 1);
                if (p < MAXC) scand[(r0 + 8) * MAXC + p] = k0;
            }
            if (tE3 < thr1) {
                int p = atomicAdd(&scnt[r0 + 8], 1);
                if (p < MAXC) scand[(r0 + 8) * MAXC + p] = k0 + 1;
            }
            if (tO2 < thr1) {
                int p = atomicAdd(&scnt[r0 + 8], 1);
                if (p < MAXC) scand[(r0 + 8) * MAXC + p] = k1;
            }
            if (tO3 < thr1) {
                int p = atomicAdd(&scnt[r0 + 8], 1);
                if (p < MAXC) scand[(r0 + 8) * MAXC + p] = k1 + 1;
            }
        }
    }
    __syncthreads();

    // ---- exact rescore: pair-split candidates, u64-key argmin merge ----
    const int vid = blockIdx.x * M_TILE + row;
    const float4* xr = (const float4*)(x + (size_t)vid * D_DIM);
    {
        const float A = san[row];
        int nc = scnt[row];
        if (nc > MAXC) {                 // overflow: split full exact scan
            for (int k = half; k < K_CODES; k += 2) {
                float s = exact_score(cb, xr, A, scn[k], k);
                atomicMin(&skey[row], ((u64)__float_as_uint(s) << 32) | (u32)k);
            }
        } else {
            const int* cl = scand + row * MAXC;
            for (int i = half; i < nc; i += 2) {
                int k = cl[i];
                float s = exact_score(cb, xr, A, scn[k], k);
                // s > 0 (dist^2 ~ 64): float-bits order == value order.
                atomicMin(&skey[row], ((u64)__float_as_uint(s) << 32) | (u32)k);
            }
        }
    }
    __syncthreads();

    const int bi = (int)(u32)skey[row];
    if (half == 0) {
        outidx[vid] = (float)bi;
        atomicAdd(&g_hist[bi], 1);
    }

    // ---- epilogue: 2 threads/row, 32 floats each ----
    // quantized_st = x + (q - x); SSE of (q - x)^2.
    // outq is d_out+1 (odd float offset): scalar 32-bit stores only.
    float sse = 0.f;
    {
        const float4* qr = (const float4*)(cb + bi * D_DIM) + half * 8;
        const float4* xh = xr + half * 8;
        float* o = outq + (size_t)vid * D_DIM + half * 32;
#pragma unroll
        for (int j = 0; j < 8; j++) {
            float4 qv = qr[j], xv = xh[j];
            float d0 = __fadd_rn(qv.x, -xv.x), d1 = __fadd_rn(qv.y, -xv.y);
            float d2 = __fadd_rn(qv.z, -xv.z), d3 = __fadd_rn(qv.w, -xv.w);
            sse += d0 * d0 + d1 * d1 + d2 * d2 + d3 * d3;
            o[4 * j]     = __fadd_rn(xv.x, d0);
            o[4 * j + 1] = __fadd_rn(xv.y, d1);
            o[4 * j + 2] = __fadd_rn(xv.z, d2);
            o[4 * j + 3] = __fadd_rn(xv.w, d3);
        }
    }

    // Block-reduce SSE -> one double atomic per CTA
#pragma unroll
    for (int o = 16; o > 0; o >>= 1)
        sse += __shfl_xor_sync(0xFFFFFFFFu, sse, o);
    if ((tid & 31) == 0) sred[tid >> 5] = (double)sse;
    __syncthreads();
    if (tid == 0) {
        double s = 0.0;
#pragma unroll
        for (int w = 0; w < 8; w++) s += sred[w];
        atomicAdd(&g_sse, s);
        __threadfence();
        slast[0] = (atomicAdd(&g_done, 1u) == (u32)(TILES - 1));
    }
    __syncthreads();

    // ---- last CTA: finalize loss + perplexity, reset accumulators ----
    if (slast[0]) {
        __threadfence();
        int h0 = atomicAdd(&g_hist[tid], 0);
        int h1 = atomicAdd(&g_hist[tid + 256], 0);
        const float n = (float)(nd / D_DIM);
        float p0 = (float)h0 / n, p1 = (float)h1 / n;
        float e = p0 * logf(p0 + 1e-10f) + p1 * logf(p1 + 1e-10f);
#pragma unroll
        for (int o = 16; o > 0; o >>= 1)
            e += __shfl_xor_sync(0xFFFFFFFFu, e, o);
        float* red = (float*)sred;   // reuse (sse phase done)
        __syncthreads();
        if ((tid & 31) == 0) red[tid >> 5] = e;
        __syncthreads();
        if (tid == 0) {
            float v = red[0] + red[1] + red[2] + red[3] +
                      red[4] + red[5] + red[6] + red[7];
            double ssum = atomicAdd(&g_sse, 0.0);
            out[1 + nd] = expf(-v);                // perplexity
            float m = (float)(ssum / (double)nd);  // mean squared error
            out[0] = m + 0.25f * m;                // q_loss + 0.25*e_loss
            g_sse = 0.0;                           // reset for next replay
            g_done = 0;
        }
        g_hist[tid] = 0;
        g_hist[tid + 256] = 0;
    }
}

// ---------------------------------------------------------------------------
extern "C" void kernel_launch(void* const* d_in, const int* in_sizes, int n_in,
                              void* d_out, int out_size) {
    const float* x  = (const float*)d_in[0];
    const float* cb = (const float*)d_in[1];
    float* out = (float*)d_out;

    int nd = in_sizes[0];   // 4194304

    cudaFuncSetAttribute(vq_main, cudaFuncAttributeMaxDynamicSharedMemorySize,
                         SMEM_SZ);

    vq_main<<<TILES, TPB, SMEM_SZ>>>(x, cb, out, nd);
}

// round 17
// speedup vs baseline: 1.6679x; 1.6190x over previous
#include <cuda_runtime.h>
#include <cuda_bf16.h>
#include <cuda_fp16.h>
#include <cstdint>
#include <math.h>

// VectorQuantizer N=65536, D=64, K=512.
// R17: R16 single kernel + ALL bulk global accesses coalesced via
// warp-cooperative row processing (fills, norms via half-warp butterflies,
// epilogue). Screen = x4-paired two-phase HMMA; rescore untouched.
// d_out: [0]=loss, [1..ND]=q_st, [1+ND]=ppl, [2+ND..)=idx.

#define D_DIM   64
#define K_CODES 512
#define M_TILE  128
#define TILES   512          // 65536 / 128
#define TPB     256
#define EPS     5e-3f        // >= 2x two-sided worst-case bf16 screen error
#define MAXC    24

typedef unsigned int u32;
typedef unsigned long long u64;

__device__ int    g_hist[K_CODES];   // reset by last CTA
__device__ double g_sse;             // reset by last CTA
__device__ u32    g_done;            // reset by last CTA

__device__ __forceinline__ u32 smem_u32(const void* p) {
    u32 a;
    asm("{ .reg .u64 t; cvta.to.shared.u64 t, %1; cvt.u32.u64 %0, t; }"
        : "=r"(a) : "l"(p));
    return a;
}
__device__ __forceinline__ u32 sw128(u32 b) { return b ^ ((b >> 3) & 0x70); }

__device__ __forceinline__ void ldsm_x4(u32& r0, u32& r1, u32& r2, u32& r3, u32 a) {
    asm volatile("ldmatrix.sync.aligned.m8n8.x4.shared.b16 {%0,%1,%2,%3}, [%4];"
                 : "=r"(r0), "=r"(r1), "=r"(r2), "=r"(r3) : "r"(a));
}
__device__ __forceinline__ void mma16816(float& c0, float& c1, float& c2, float& c3,
                                         u32 a0, u32 a1, u32 a2, u32 a3,
                                         u32 b0, u32 b1) {
    asm volatile(
        "mma.sync.aligned.m16n8k16.row.col.f32.bf16.bf16.f32 "
        "{%0,%1,%2,%3}, {%4,%5,%6,%7}, {%8,%9}, {%0,%1,%2,%3};"
        : "+f"(c0), "+f"(c1), "+f"(c2), "+f"(c3)
        : "r"(a0), "r"(a1), "r"(a2), "r"(a3), "r"(b0), "r"(b1));
}

// ---- smem layout (bytes), ~96 KB -> 2 CTAs/SM ----
#define SM_A    0                        // 128 rows * 128B bf16 (SW128) = 16384
#define SM_B    16384                    // 512 rows * 128B bf16 (SW128) = 65536
#define SM_CN   81920                    // 512 f32 = 2048
#define SM_AN   83968                    // 128 f32 = 512
#define SM_CNT  84480                    // 128 int = 512
#define SM_CAND 84992                    // 128*24 int = 12288
#define SM_KEY  97280                    // 128 u64 = 1024
#define SM_RED  98304                    // 8 double = 64
#define SM_LAST 98368                    // 1 u32 (+pad) = 64
#define SMEM_SZ 98432

// Exact fp32 score s = fl( fl(A - 2*dot) + C ), 4-chain fp32 dot.
__device__ __forceinline__ float exact_score(const float* __restrict__ cb,
                                             const float4* __restrict__ xr,
                                             float A, float C, int k) {
    const float4* cr = (const float4*)(cb + k * D_DIM);
    float a0 = 0.f, a1 = 0.f, a2 = 0.f, a3 = 0.f;
#pragma unroll
    for (int j = 0; j < D_DIM / 4; j++) {
        float4 cv = cr[j], xv = xr[j];
        a0 = __fmaf_rn(xv.x, cv.x, a0);
        a1 = __fmaf_rn(xv.y, cv.y, a1);
        a2 = __fmaf_rn(xv.z, cv.z, a2);
        a3 = __fmaf_rn(xv.w, cv.w, a3);
    }
    float dot = (a0 + a1) + (a2 + a3);
    return __fadd_rn(__fmaf_rn(-2.f, dot, A), C);
}

// Coalesced fill: warp converts rows [base, base+nr) of src (fp32, 64/row)
// into bf16 SW128 at smem dst; fp32 row norms -> norm_out.
// Two rows per iteration: lanes 0-15 row r, lanes 16-31 row r+1.
__device__ __forceinline__ void fill_rows(const float* __restrict__ src,
                                          char* smem_dst, float* norm_out,
                                          int base, int nr, int lane) {
    const int q = lane & 15;
    const int sub = lane >> 4;
#pragma unroll 4
    for (int it = 0; it < nr / 2; it++) {
        int r = base + it * 2 + sub;
        float4 v = *(const float4*)(src + (size_t)r * D_DIM + q * 4);
        float p = ((__fmul_rn(v.x, v.x) + __fmul_rn(v.y, v.y)) +
                   (__fmul_rn(v.z, v.z) + __fmul_rn(v.w, v.w)));
        __nv_bfloat162 b0 = __floats2bfloat162_rn(v.x, v.y);
        __nv_bfloat162 b1 = __floats2bfloat162_rn(v.z, v.w);
        *(uint2*)(smem_dst + sw128((u32)(r & 511) * 128 + q * 8)) =
            make_uint2(*(u32*)&b0, *(u32*)&b1);
        p += __shfl_xor_sync(0xFFFFFFFFu, p, 1);
        p += __shfl_xor_sync(0xFFFFFFFFu, p, 2);
        p += __shfl_xor_sync(0xFFFFFFFFu, p, 4);
        p += __shfl_xor_sync(0xFFFFFFFFu, p, 8);
        if (q == 0) norm_out[r & 511] = p;
    }
}

// ---------------------------------------------------------------------------
__global__ __launch_bounds__(TPB, 2)
void vq_main(const float* __restrict__ x, const float* __restrict__ cb,
             float* __restrict__ out, int nd) {
    extern __shared__ char smem[];
    const u32 sb  = smem_u32(smem);
    const int tid = threadIdx.x;
    const int lane = tid & 31;
    const int wid = tid >> 5;
    const int wrow = wid * 16;                      // warp's first local row

    float* outq   = out + 1;
    float* outidx = out + 2 + nd;

    float*  scn  = (float*)(smem + SM_CN);
    float*  san  = (float*)(smem + SM_AN);
    int*    scnt = (int*)(smem + SM_CNT);
    int*    scand= (int*)(smem + SM_CAND);
    u64*    skey = (u64*)(smem + SM_KEY);
    double* sred = (double*)(smem + SM_RED);
    u32*    slast= (u32*)(smem + SM_LAST);

    // B fill: warp w handles cb rows [w*64, w*64+64), fully coalesced.
    fill_rows(cb, smem + SM_B, scn, wid * 64, 64, lane);
    // A fill: warp w handles x rows [tile_base + w*16, +16), coalesced.
    {
        const float* xt = x + (size_t)blockIdx.x * M_TILE * D_DIM;
        fill_rows(xt, smem + SM_A, san, wrow, 16, lane);
    }
    if (tid < M_TILE) { scnt[tid] = 0; skey[tid] = ~0ull; }
    __syncthreads();

    // ---- screening: each warp handles rows [wrow, wrow+16) x 512 codes ----
    {
        u32 af[4][4];
        {
            int r  = (lane & 7) + ((lane & 8) ? 8 : 0);
            int hh = (lane >> 4) & 1;
            u32 abase = (u32)(wrow + r) * 128 + hh * 16;
#pragma unroll
            for (int ks = 0; ks < 4; ks++)
                ldsm_x4(af[ks][0], af[ks][1], af[ks][2], af[ks][3],
                        sb + SM_A + sw128(abase + ks * 32));
        }
        // x4 B addressing: groups 0/1 -> even tile (b0/b1), 2/3 -> odd tile
        const u32 bbase4 = (u32)(lane & 7) * 128 + ((lane >> 3) & 1) * 16
                         + (u32)(lane >> 4) * 1024;
        const int r0 = wrow + (lane >> 2);
        const int nlo = (lane & 3) * 2;

        // Phase 1: true row screen minima, tile-pair loop (branch-free)
        float tb0 = 3.4e38f, tb1 = 3.4e38f;
#pragma unroll 2
        for (int pr = 0; pr < 32; pr++) {
            float e0 = 0.f, e1 = 0.f, e2 = 0.f, e3 = 0.f;
            float o0 = 0.f, o1 = 0.f, o2 = 0.f, o3 = 0.f;
            u32 pb = (u32)pr * 2048;
#pragma unroll
            for (int ks = 0; ks < 4; ks++) {
                u32 b0, b1, b2, b3;
                ldsm_x4(b0, b1, b2, b3, sb + SM_B + sw128(pb + bbase4 + ks * 32));
                mma16816(e0, e1, e2, e3,
                         af[ks][0], af[ks][1], af[ks][2], af[ks][3], b0, b1);
                mma16816(o0, o1, o2, o3,
                         af[ks][0], af[ks][1], af[ks][2], af[ks][3], b2, b3);
            }
            int k0 = pr * 16 + nlo;
            int k1 = k0 + 8;
            float cnE0 = scn[k0], cnE1 = scn[k0 + 1];
            float cnO0 = scn[k1], cnO1 = scn[k1 + 1];
            tb0 = fminf(tb0, fminf(fminf(__fmaf_rn(-2.f, e0, cnE0),
                                         __fmaf_rn(-2.f, e1, cnE1)),
                                   fminf(__fmaf_rn(-2.f, o0, cnO0),
                                         __fmaf_rn(-2.f, o1, cnO1))));
            tb1 = fminf(tb1, fminf(fminf(__fmaf_rn(-2.f, e2, cnE0),
                                         __fmaf_rn(-2.f, e3, cnE1)),
                                   fminf(__fmaf_rn(-2.f, o2, cnO0),
                                         __fmaf_rn(-2.f, o3, cnO1))));
        }
        tb0 = fminf(tb0, __shfl_xor_sync(0xFFFFFFFFu, tb0, 1));
        tb0 = fminf(tb0, __shfl_xor_sync(0xFFFFFFFFu, tb0, 2));
        tb1 = fminf(tb1, __shfl_xor_sync(0xFFFFFFFFu, tb1, 1));
        tb1 = fminf(tb1, __shfl_xor_sync(0xFFFFFFFFu, tb1, 2));
        const float thr0 = tb0 + EPS, thr1 = tb1 + EPS;

        // Phase 2: recompute (paired), push candidates vs fixed thresholds
#pragma unroll 2
        for (int pr = 0; pr < 32; pr++) {
            float e0 = 0.f, e1 = 0.f, e2 = 0.f, e3 = 0.f;
            float o0 = 0.f, o1 = 0.f, o2 = 0.f, o3 = 0.f;
            u32 pb = (u32)pr * 2048;
#pragma unroll
            for (int ks = 0; ks < 4; ks++) {
                u32 b0, b1, b2, b3;
                ldsm_x4(b0, b1, b2, b3, sb + SM_B + sw128(pb + bbase4 + ks * 32));
                mma16816(e0, e1, e2, e3,
                         af[ks][0], af[ks][1], af[ks][2], af[ks][3], b0, b1);
                mma16816(o0, o1, o2, o3,
                         af[ks][0], af[ks][1], af[ks][2], af[ks][3], b2, b3);
            }
            int k0 = pr * 16 + nlo;
            int k1 = k0 + 8;
            float cnE0 = scn[k0], cnE1 = scn[k0 + 1];
            float cnO0 = scn[k1], cnO1 = scn[k1 + 1];
            float tE0 = __fmaf_rn(-2.f, e0, cnE0);
            float tE1 = __fmaf_rn(-2.f, e1, cnE1);
            float tE2 = __fmaf_rn(-2.f, e2, cnE0);
            float tE3 = __fmaf_rn(-2.f, e3, cnE1);
            float tO0 = __fmaf_rn(-2.f, o0, cnO0);
            float tO1 = __fmaf_rn(-2.f, o1, cnO1);
            float tO2 = __fmaf_rn(-2.f, o2, cnO0);
            float tO3 = __fmaf_rn(-2.f, o3, cnO1);
            if (tE0 < thr0) {
                int p = atomicAdd(&scnt[r0], 1);
                if (p < MAXC) scand[r0 * MAXC + p] = k0;
            }
            if (tE1 < thr0) {
                int p = atomicAdd(&scnt[r0], 1);
                if (p < MAXC) scand[r0 * MAXC + p] = k0 + 1;
            }
            if (tO0 < thr0) {
                int p = atomicAdd(&scnt[r0], 1);
                if (p < MAXC) scand[r0 * MAXC + p] = k1;
            }
            if (tO1 < thr0) {
                int p = atomicAdd(&scnt[r0], 1);
                if (p < MAXC) scand[r0 * MAXC + p] = k1 + 1;
            }
            if (tE2 < thr1) {
                int p = atomicAdd(&scnt[r0 + 8], 1);
                if (p < MAXC) scand[(r0 + 8) * MAXC + p] = k0;
            }
            if (tE3 < thr1) {
                int p = atomicAdd(&scnt[r0 + 8], 1);
                if (p < MAXC) scand[(r0 + 8) * MAXC + p] = k0 + 1;
            }
            if (tO2 < thr1) {
                int p = atomicAdd(&scnt[r0 + 8], 1);
                if (p < MAXC) scand[(r0 + 8) * MAXC + p] = k1;
            }
            if (tO3 < thr1) {
                int p = atomicAdd(&scnt[r0 + 8], 1);
                if (p < MAXC) scand[(r0 + 8) * MAXC + p] = k1 + 1;
            }
        }
    }
    __syncthreads();

    // ---- exact rescore: pair-split candidates, u64-key argmin merge ----
    {
        const int row  = tid & 127;
        const int half = tid >> 7;
        const int vid = blockIdx.x * M_TILE + row;
        const float4* xr = (const float4*)(x + (size_t)vid * D_DIM);
        const float A = san[row];
        int nc = scnt[row];
        if (nc > MAXC) {                 // overflow: split full exact scan
            for (int k = half; k < K_CODES; k += 2) {
                float s = exact_score(cb, xr, A, scn[k], k);
                atomicMin(&skey[row], ((u64)__float_as_uint(s) << 32) | (u32)k);
            }
        } else {
            const int* cl = scand + row * MAXC;
            for (int i = half; i < nc; i += 2) {
                int k = cl[i];
                float s = exact_score(cb, xr, A, scn[k], k);
                // s > 0 (dist^2 ~ 64): float-bits order == value order.
                atomicMin(&skey[row], ((u64)__float_as_uint(s) << 32) | (u32)k);
            }
        }
    }
    __syncthreads();

    // ---- outputs ----
    if (tid < M_TILE) {                  // coalesced index write + histogram
        int b = (int)(u32)skey[tid];
        outidx[blockIdx.x * M_TILE + tid] = (float)b;
        atomicAdd(&g_hist[b], 1);
    }

    // Epilogue: warp-cooperative per row -> ALL accesses coalesced.
    // quantized_st = x + (q - x); SSE of (q - x)^2.
    // outq is d_out+1 (odd float): scalar 32-bit stores only (coalesced).
    float sse = 0.f;
#pragma unroll 4
    for (int it = 0; it < 16; it++) {
        int r = wrow + it;
        int b = (int)(u32)skey[r];
        size_t xb = ((size_t)blockIdx.x * M_TILE + r) * D_DIM;
        float x0 = x[xb + lane], x1 = x[xb + 32 + lane];
        float q0 = cb[(size_t)b * D_DIM + lane];
        float q1 = cb[(size_t)b * D_DIM + 32 + lane];
        float d0 = __fadd_rn(q0, -x0), d1 = __fadd_rn(q1, -x1);
        sse += d0 * d0 + d1 * d1;
        outq[xb + lane]      = __fadd_rn(x0, d0);
        outq[xb + 32 + lane] = __fadd_rn(x1, d1);
    }

    // Block-reduce SSE -> one double atomic per CTA
#pragma unroll
    for (int o = 16; o > 0; o >>= 1)
        sse += __shfl_xor_sync(0xFFFFFFFFu, sse, o);
    if (lane == 0) sred[wid] = (double)sse;
    __syncthreads();
    if (tid == 0) {
        double s = 0.0;
#pragma unroll
        for (int w = 0; w < 8; w++) s += sred[w];
        atomicAdd(&g_sse, s);
        __threadfence();
        slast[0] = (atomicAdd(&g_done, 1u) == (u32)(TILES - 1));
    }
    __syncthreads();

    // ---- last CTA: finalize loss + perplexity, reset accumulators ----
    if (slast[0]) {
        __threadfence();
        int h0 = atomicAdd(&g_hist[tid], 0);
        int h1 = atomicAdd(&g_hist[tid + 256], 0);
        const float n = (float)(nd / D_DIM);
        float p0 = (float)h0 / n, p1 = (float)h1 / n;
        float e = p0 * logf(p0 + 1e-10f) + p1 * logf(p1 + 1e-10f);
#pragma unroll
        for (int o = 16; o > 0; o >>= 1)
            e += __shfl_xor_sync(0xFFFFFFFFu, e, o);
        float* red = (float*)sred;   // reuse (sse phase done)
        __syncthreads();
        if (lane == 0) red[wid] = e;
        __syncthreads();
        if (tid == 0) {
            float v = red[0] + red[1] + red[2] + red[3] +
                      red[4] + red[5] + red[6] + red[7];
            double ssum = atomicAdd(&g_sse, 0.0);
            out[1 + nd] = expf(-v);                // perplexity
            float m = (float)(ssum / (double)nd);  // mean squared error
            out[0] = m + 0.25f * m;                // q_loss + 0.25*e_loss
            g_sse = 0.0;                           // reset for next replay
            g_done = 0;
        }
        g_hist[tid] = 0;
        g_hist[tid + 256] = 0;
    }
}

// ---------------------------------------------------------------------------
extern "C" void kernel_launch(void* const* d_in, const int* in_sizes, int n_in,
                              void* d_out, int out_size) {
    const float* x  = (const float*)d_in[0];
    const float* cb = (const float*)d_in[1];
    float* out = (float*)d_out;

    int nd = in_sizes[0];   // 4194304

    cudaFuncSetAttribute(vq_main, cudaFuncAttributeMaxDynamicSharedMemorySize,
                         SMEM_SZ);

    vq_main<<<TILES, TPB, SMEM_SZ>>>(x, cb, out, nd);
}